// round 14
// baseline (speedup 1.0000x reference)
#include <cuda_runtime.h>
#include <cuda_fp16.h>
#include <cstdint>
#include <math.h>

// Problem constants
constexpr int BATCH = 4;
constexpr int CH    = 256;
constexpr int SPA   = 4096;
constexpr int NGRP  = 8;
constexpr int CPG   = CH / NGRP;
constexpr int NH    = 4;
constexpr int HD    = CH / NH;    // 64
constexpr float EPS = 1e-5f;
constexpr float SCALE = 0.125f;

constexpr int GRP_ELEMS = CPG * SPA;
constexpr int PARTS = 32;

// Scratch
__device__ __half g_qkv[(size_t)BATCH * 3*CH * SPA];  // 24 MB
__device__ __half g_ao [(size_t)BATCH * CH  * SPA];   // 8 MB
__device__ float g_part[BATCH * NGRP][PARTS][2];
__device__ float g_ga[BATCH * CH];
__device__ float g_be[BATCH * CH];

// ---------------------------------------------------------------------------
// Helpers
// ---------------------------------------------------------------------------
__device__ __forceinline__ uint32_t smem_u32(const void* p) {
    return (uint32_t)__cvta_generic_to_shared(p);
}
__device__ __forceinline__ uint32_t packh(float lo, float hi) {
    __half2 t = __floats2half2_rn(lo, hi);   // .x = lo = low 16 bits
    return *reinterpret_cast<uint32_t*>(&t);
}
__device__ __forceinline__ uint32_t h2exp2(uint32_t a) {
    uint32_t r;
    asm("ex2.approx.f16x2 %0, %1;" : "=r"(r) : "r"(a));
    return r;
}
__device__ __forceinline__ void mma_f16(float* d, const uint32_t* a,
                                        const uint32_t* b) {
    asm volatile(
        "mma.sync.aligned.m16n8k16.row.col.f32.f16.f16.f32 "
        "{%0,%1,%2,%3}, {%4,%5,%6,%7}, {%8,%9}, {%0,%1,%2,%3};\n"
        : "+f"(d[0]), "+f"(d[1]), "+f"(d[2]), "+f"(d[3])
        : "r"(a[0]), "r"(a[1]), "r"(a[2]), "r"(a[3]), "r"(b[0]), "r"(b[1]));
}
__device__ __forceinline__ void ldsm_x4(uint32_t* r, uint32_t addr) {
    asm volatile("ldmatrix.sync.aligned.m8n8.x4.shared.b16 {%0,%1,%2,%3}, [%4];\n"
                 : "=r"(r[0]), "=r"(r[1]), "=r"(r[2]), "=r"(r[3]) : "r"(addr));
}
__device__ __forceinline__ void ldsm_x4_t(uint32_t* r, uint32_t addr) {
    asm volatile("ldmatrix.sync.aligned.m8n8.x4.trans.shared.b16 {%0,%1,%2,%3}, [%4];\n"
                 : "=r"(r[0]), "=r"(r[1]), "=r"(r[2]), "=r"(r[3]) : "r"(addr));
}
__device__ __forceinline__ void cpa(uint32_t dst, const void* src) {
    asm volatile("cp.async.cg.shared.global [%0], [%1], 16;\n" :: "r"(dst), "l"(src));
}
#define CP_COMMIT() asm volatile("cp.async.commit_group;\n" ::: "memory")
#define CP_WAIT0()  asm volatile("cp.async.wait_group 0;\n" ::: "memory")
#define CP_WAIT1()  asm volatile("cp.async.wait_group 1;\n" ::: "memory")

// ---------------------------------------------------------------------------
// GroupNorm stats
// ---------------------------------------------------------------------------
__global__ __launch_bounds__(256) void k_gn_part(const float* __restrict__ x) {
    int part = blockIdx.x & (PARTS - 1);
    int bg   = blockIdx.x / PARTS;
    const float4* base = reinterpret_cast<const float4*>(x + (size_t)bg * GRP_ELEMS)
                         + (size_t)part * (GRP_ELEMS / PARTS / 4);
    const int n4 = GRP_ELEMS / PARTS / 4;
    float s = 0.f, s2 = 0.f;
    for (int i = threadIdx.x; i < n4; i += 256) {
        float4 v = base[i];
        s  += v.x + v.y + v.z + v.w;
        s2 += v.x*v.x + v.y*v.y + v.z*v.z + v.w*v.w;
    }
    __shared__ float sh[16];
    for (int o = 16; o; o >>= 1) {
        s  += __shfl_xor_sync(0xffffffffu, s,  o);
        s2 += __shfl_xor_sync(0xffffffffu, s2, o);
    }
    if ((threadIdx.x & 31) == 0) { int w = threadIdx.x >> 5; sh[w*2] = s; sh[w*2+1] = s2; }
    __syncthreads();
    if (threadIdx.x == 0) {
        float a = 0.f, b = 0.f;
        #pragma unroll
        for (int i = 0; i < 8; i++) { a += sh[i*2]; b += sh[i*2+1]; }
        g_part[bg][part][0] = a; g_part[bg][part][1] = b;
    }
}

// finalize stats + per-(b,c) GN coefficients (ga, be)
__global__ __launch_bounds__(1024) void k_gn_final(const float* __restrict__ gamma,
                                                   const float* __restrict__ beta) {
    __shared__ float sm_m[32], sm_r[32];
    int t = threadIdx.x;
    if (t < BATCH * NGRP) {
        float s = 0.f, s2 = 0.f;
        #pragma unroll
        for (int p = 0; p < PARTS; p++) { s += g_part[t][p][0]; s2 += g_part[t][p][1]; }
        const float invN = 1.0f / (float)GRP_ELEMS;
        float mean = s * invN;
        float var  = s2 * invN - mean * mean;
        sm_m[t] = mean; sm_r[t] = rsqrtf(var + EPS);
    }
    __syncthreads();
    if (t < BATCH * CH) {
        int b = t >> 8, c = t & 255;
        int bg = b * NGRP + (c >> 5);
        float ga = gamma[c] * sm_r[bg];
        g_ga[t] = ga;
        g_be[t] = beta[c] - sm_m[bg] * ga;
    }
}

// ---------------------------------------------------------------------------
// f16 mma GEMM: Y[b][o][s] = sum_c W[o][c]*X[b][c][s] + bias (+resid)
// GN=true: X is fp32 `x`, normalized on the fly via g_ga/g_be.
// GN=false: X is __half (g_ao).
// ---------------------------------------------------------------------------
template<bool GN, bool RESID, typename OT>
__global__ __launch_bounds__(256, 2) void k_gemm(const float* __restrict__ Wm,
                                                 const float* __restrict__ bias,
                                                 const void* __restrict__ Xv,
                                                 OT* __restrict__ Y,
                                                 const float* __restrict__ resid,
                                                 int M) {
    __shared__ __half As[128 * 40];
    __shared__ __half Bs[32 * 136];

    const int b  = blockIdx.z;
    const int o0 = blockIdx.y * 128;
    const int s0 = blockIdx.x * 128;
    const int tid = threadIdx.x, lane = tid & 31, wid = tid >> 5;
    const int wm = wid & 3, wn = wid >> 2;
    const int lrow = lane & 7, lmat = lane >> 3;

    float acc[2][8][4] = {};

    for (int k0 = 0; k0 < CH; k0 += 32) {
        // A: W tile fp32 -> f16
        #pragma unroll
        for (int r = 0; r < 4; r++) {
            int i = tid + r * 256;
            int row = i >> 3, kq = (i & 7) * 4;
            float4 w4 = *reinterpret_cast<const float4*>(
                            Wm + (size_t)(o0 + row) * CH + k0 + kq);
            uint2 wp = {packh(w4.x, w4.y), packh(w4.z, w4.w)};
            *reinterpret_cast<uint2*>(&As[row * 40 + kq]) = wp;
        }
        // B tile
        #pragma unroll
        for (int r = 0; r < 2; r++) {
            int i = tid + r * 256;
            int kr = i >> 4, s8 = (i & 15) * 8;
            if (GN) {
                const float* Xb = (const float*)Xv + (size_t)b * CH * SPA;
                const float* xp = Xb + (size_t)(k0 + kr) * SPA + s0 + s8;
                float ga = g_ga[b * CH + k0 + kr];
                float be = g_be[b * CH + k0 + kr];
                float4 x0 = *reinterpret_cast<const float4*>(xp);
                float4 x1 = *reinterpret_cast<const float4*>(xp + 4);
                uint4 wv;
                wv.x = packh(x0.x*ga+be, x0.y*ga+be);
                wv.y = packh(x0.z*ga+be, x0.w*ga+be);
                wv.z = packh(x1.x*ga+be, x1.y*ga+be);
                wv.w = packh(x1.z*ga+be, x1.w*ga+be);
                *reinterpret_cast<uint4*>(&Bs[kr * 136 + s8]) = wv;
            } else {
                const __half* Xb = (const __half*)Xv + (size_t)b * CH * SPA;
                uint4 xv = *reinterpret_cast<const uint4*>(
                                Xb + (size_t)(k0 + kr) * SPA + s0 + s8);
                *reinterpret_cast<uint4*>(&Bs[kr * 136 + s8]) = xv;
            }
        }
        __syncthreads();

        #pragma unroll
        for (int kk = 0; kk < 32; kk += 16) {
            uint32_t a[2][4];
            #pragma unroll
            for (int mt = 0; mt < 2; mt++) {
                uint32_t ad = smem_u32(&As[(wm*32 + mt*16 + (lmat & 1)*8 + lrow)*40
                                           + kk + (lmat >> 1)*8]);
                ldsm_x4(a[mt], ad);
            }
            #pragma unroll
            for (int ntp = 0; ntp < 8; ntp += 2) {
                uint32_t bf[4];
                uint32_t ad = smem_u32(&Bs[(kk + (lmat & 1)*8 + lrow)*136
                                           + wn*64 + (ntp + (lmat >> 1))*8]);
                ldsm_x4_t(bf, ad);
                #pragma unroll
                for (int mt = 0; mt < 2; mt++) {
                    mma_f16(acc[mt][ntp],     a[mt], bf);
                    mma_f16(acc[mt][ntp + 1], a[mt], bf + 2);
                }
            }
        }
        __syncthreads();
    }

    #pragma unroll
    for (int mt = 0; mt < 2; mt++) {
        int row0 = o0 + wm * 32 + mt * 16 + (lane >> 2);
        float bv0 = bias[row0], bv1 = bias[row0 + 8];
        #pragma unroll
        for (int nt = 0; nt < 8; nt++) {
            int col = s0 + wn * 64 + nt * 8 + 2 * (lane & 3);
            size_t off0 = ((size_t)b * M + row0) * SPA + col;
            size_t off1 = ((size_t)b * M + row0 + 8) * SPA + col;
            float r00 = acc[mt][nt][0] + bv0, r01 = acc[mt][nt][1] + bv0;
            float r10 = acc[mt][nt][2] + bv1, r11 = acc[mt][nt][3] + bv1;
            if (RESID) {
                float2 x0 = *reinterpret_cast<const float2*>(&resid[off0]);
                float2 x1 = *reinterpret_cast<const float2*>(&resid[off1]);
                r00 += x0.x; r01 += x0.y; r10 += x1.x; r11 += x1.y;
            }
            if (sizeof(OT) == 2) {
                uint32_t p0 = packh(r00, r01), p1 = packh(r10, r11);
                *reinterpret_cast<uint32_t*>(&Y[off0]) = p0;
                *reinterpret_cast<uint32_t*>(&Y[off1]) = p1;
            } else {
                *reinterpret_cast<float2*>(&Y[off0]) = make_float2(r00, r01);
                *reinterpret_cast<float2*>(&Y[off1]) = make_float2(r10, r11);
            }
        }
    }
}

// ---------------------------------------------------------------------------
// Flash attention, f16 mma + ldmatrix, cp.async double-buffered K/V.
// Block = (b,h) x 128 queries; warp w owns q rows [w*16, w*16+16), full keys.
// Q/K/V in [d][*] SMEM layout.
// ---------------------------------------------------------------------------
constexpr int QT = 128;
constexpr int KT = 64;
constexpr int NTILE = SPA / KT;   // 64
constexpr int QS_STR = 136;       // halves
constexpr int KV_STR = 72;        // halves

constexpr int SM_Q  = 0;                       // 64*136*2 = 17408
constexpr int SM_K0 = 17408;                   // 64*72*2  = 9216
constexpr int SM_K1 = SM_K0 + 9216;
constexpr int SM_V0 = SM_K1 + 9216;
constexpr int SM_V1 = SM_V0 + 9216;
constexpr int SM_ATTN = SM_V1 + 9216;          // 54272

__global__ __launch_bounds__(256, 2) void k_attn() {
    extern __shared__ uint8_t smraw[];
    __half* Qs = reinterpret_cast<__half*>(smraw + SM_Q);
    __half* Ks[2] = { reinterpret_cast<__half*>(smraw + SM_K0),
                      reinterpret_cast<__half*>(smraw + SM_K1) };
    __half* Vs[2] = { reinterpret_cast<__half*>(smraw + SM_V0),
                      reinterpret_cast<__half*>(smraw + SM_V1) };

    const int bh = blockIdx.y, b = bh >> 2, h = bh & 3;
    const __half* qb = g_qkv + ((size_t)b * 3 * CH + h * HD) * SPA;
    const __half* kb = qb + (size_t)CH * SPA;
    const __half* vb = qb + (size_t)2 * CH * SPA;
    const int q0 = blockIdx.x * QT;
    const int tid = threadIdx.x, lane = tid & 31, w = tid >> 5;
    const int lrow = lane & 7, lmat = lane >> 3;

    const uint32_t qs_a = smem_u32(Qs);
    const uint32_t ks_a[2] = { smem_u32(Ks[0]), smem_u32(Ks[1]) };
    const uint32_t vs_a[2] = { smem_u32(Vs[0]), smem_u32(Vs[1]) };

    // prologue: Q + K0/V0 (group A), K1/V1 (group B)
    #pragma unroll
    for (int r = 0; r < 4; r++) {           // Q: 1024 chunks of 16B
        int i = tid + r * 256;
        int dd = i >> 4, q8 = (i & 15) * 8;
        cpa(qs_a + (dd * QS_STR + q8) * 2, qb + (size_t)dd * SPA + q0 + q8);
    }
    #pragma unroll
    for (int r = 0; r < 2; r++) {           // K0 + V0: 512 chunks each
        int i = tid + r * 256;
        int dd = i >> 3, k8 = (i & 7) * 8;
        cpa(ks_a[0] + (dd * KV_STR + k8) * 2, kb + (size_t)dd * SPA + k8);
        cpa(vs_a[0] + (dd * KV_STR + k8) * 2, vb + (size_t)dd * SPA + k8);
    }
    CP_COMMIT();
    #pragma unroll
    for (int r = 0; r < 2; r++) {
        int i = tid + r * 256;
        int dd = i >> 3, k8 = (i & 7) * 8;
        cpa(ks_a[1] + (dd * KV_STR + k8) * 2, kb + (size_t)dd * SPA + KT + k8);
        cpa(vs_a[1] + (dd * KV_STR + k8) * 2, vb + (size_t)dd * SPA + KT + k8);
    }
    CP_COMMIT();
    CP_WAIT1();           // Q + tile0 ready
    __syncthreads();

    // hoist Q A-fragments
    uint32_t qa[4][4];
    #pragma unroll
    for (int kk4 = 0; kk4 < 4; kk4++) {
        uint32_t ad = smem_u32(&Qs[(kk4*16 + (lmat >> 1)*8 + lrow) * QS_STR
                                   + w*16 + (lmat & 1)*8]);
        ldsm_x4_t(qa[kk4], ad);
    }

    float m2[2] = {-INFINITY, -INFINITY};
    float l [2] = {0.f, 0.f};
    float o_acc[8][4] = {};
    const float CF = SCALE * 1.44269504f;

    for (int i = 0; i < NTILE; i++) {
        const __half* Kb = Ks[i & 1];
        const __half* Vb = Vs[i & 1];

        // S = Q K^T
        float sacc[8][4] = {};
        #pragma unroll
        for (int kk4 = 0; kk4 < 4; kk4++) {
            #pragma unroll
            for (int ntp = 0; ntp < 8; ntp += 2) {
                uint32_t bf[4];
                uint32_t ad = smem_u32(&Kb[(kk4*16 + (lmat & 1)*8 + lrow) * KV_STR
                                           + (ntp + (lmat >> 1))*8]);
                ldsm_x4_t(bf, ad);
                mma_f16(sacc[ntp],     qa[kk4], bf);
                mma_f16(sacc[ntp + 1], qa[kk4], bf + 2);
            }
        }

        // online softmax: p as f16x2 via ex2.approx.f16x2 (= PV A-frag regs)
        uint32_t pp[8][2];
        #pragma unroll
        for (int rh = 0; rh < 2; rh++) {
            float mx = -1e30f;
            #pragma unroll
            for (int nt = 0; nt < 8; nt++)
                mx = fmaxf(mx, fmaxf(sacc[nt][rh*2], sacc[nt][rh*2+1]));
            mx *= CF;
            mx = fmaxf(mx, __shfl_xor_sync(0xffffffffu, mx, 1));
            mx = fmaxf(mx, __shfl_xor_sync(0xffffffffu, mx, 2));
            float mnew = fmaxf(m2[rh], mx);
            __half2 sum2 = __floats2half2_rn(0.f, 0.f);
            #pragma unroll
            for (int nt = 0; nt < 8; nt++) {
                uint32_t sp = packh(sacc[nt][rh*2]   * CF - mnew,
                                    sacc[nt][rh*2+1] * CF - mnew);
                uint32_t ph = h2exp2(sp);
                pp[nt][rh] = ph;
                sum2 = __hadd2(sum2, *reinterpret_cast<__half2*>(&ph));
            }
            float2 sf = __half22float2(sum2);
            float rs = sf.x + sf.y;
            rs += __shfl_xor_sync(0xffffffffu, rs, 1);
            rs += __shfl_xor_sync(0xffffffffu, rs, 2);
            if (mx > m2[rh]) {          // max moved: rescale
                float alpha = exp2f(m2[rh] - mnew);
                #pragma unroll
                for (int nt = 0; nt < 8; nt++) {
                    o_acc[nt][rh*2]   *= alpha;
                    o_acc[nt][rh*2+1] *= alpha;
                }
                l[rh] = l[rh] * alpha + rs;
                m2[rh] = mnew;
            } else {
                l[rh] += rs;
            }
        }

        // O += P V
        #pragma unroll
        for (int j = 0; j < 4; j++) {
            uint32_t pa[4] = {pp[2*j][0], pp[2*j][1], pp[2*j+1][0], pp[2*j+1][1]};
            #pragma unroll
            for (int dt = 0; dt < 8; dt += 2) {
                uint32_t bv[4];
                uint32_t ad = smem_u32(&Vb[((dt + (lmat >> 1))*8 + lrow) * KV_STR
                                           + j*16 + (lmat & 1)*8]);
                ldsm_x4(bv, ad);
                mma_f16(o_acc[dt],     pa, bv);
                mma_f16(o_acc[dt + 1], pa, bv + 2);
            }
        }

        // rotate buffers: done reading buf[i&1]; prefetch tile i+2 into it
        __syncthreads();
        if (i + 2 < NTILE) {
            int t0 = (i + 2) * KT;
            uint32_t ka = ks_a[i & 1], va = vs_a[i & 1];
            #pragma unroll
            for (int r = 0; r < 2; r++) {
                int c = tid + r * 256;
                int dd = c >> 3, k8 = (c & 7) * 8;
                cpa(ka + (dd * KV_STR + k8) * 2, kb + (size_t)dd * SPA + t0 + k8);
                cpa(va + (dd * KV_STR + k8) * 2, vb + (size_t)dd * SPA + t0 + k8);
            }
            CP_COMMIT();
        }
        if (i + 1 < NTILE) {
            if (i + 2 < NTILE) { CP_WAIT1(); } else { CP_WAIT0(); }
            __syncthreads();
        }
    }

    // normalize + write f16: g_ao[b][h*64+dd][q0+qr]
    __half* ob = g_ao + ((size_t)b * CH + h * HD) * SPA + q0;
    #pragma unroll
    for (int rh = 0; rh < 2; rh++) {
        float inv = 1.0f / l[rh];
        int qr = w * 16 + rh * 8 + (lane >> 2);
        #pragma unroll
        for (int nt = 0; nt < 8; nt++) {
            int dd = nt * 8 + 2 * (lane & 3);
            ob[(size_t)dd * SPA + qr]       = __float2half(o_acc[nt][rh*2]   * inv);
            ob[(size_t)(dd + 1) * SPA + qr] = __float2half(o_acc[nt][rh*2+1] * inv);
        }
    }
}

// ---------------------------------------------------------------------------
extern "C" void kernel_launch(void* const* d_in, const int* in_sizes, int n_in,
                              void* d_out, int out_size) {
    const float* x      = (const float*)d_in[0];
    const float* gamma  = (const float*)d_in[1];
    const float* beta   = (const float*)d_in[2];
    const float* w_qkv  = (const float*)d_in[3];
    const float* b_qkv  = (const float*)d_in[4];
    const float* w_proj = (const float*)d_in[5];
    const float* b_proj = (const float*)d_in[6];
    float* out = (float*)d_out;

    __half *qkv_p, *ao_p;
    cudaGetSymbolAddress((void**)&qkv_p, g_qkv);
    cudaGetSymbolAddress((void**)&ao_p,  g_ao);

    cudaFuncSetAttribute(k_attn, cudaFuncAttributeMaxDynamicSharedMemorySize, SM_ATTN);

    // GroupNorm stats + coefficients
    k_gn_part <<<BATCH * NGRP * PARTS, 256>>>(x);
    k_gn_final<<<1, 1024>>>(gamma, beta);

    // QKV GEMM with fused GN (M = 768), f16 out
    {
        dim3 grid(SPA / 128, (3 * CH) / 128, BATCH);
        k_gemm<true, false, __half><<<grid, 256>>>(w_qkv, b_qkv, x, qkv_p,
                                                   nullptr, 3 * CH);
    }

    // f16 flash attention
    {
        dim3 grid(SPA / QT, BATCH * NH);
        k_attn<<<grid, 256, SM_ATTN>>>();
    }

    // Proj GEMM + residual (M = 256), fp32 out
    {
        dim3 grid(SPA / 128, CH / 128, BATCH);
        k_gemm<false, true, float><<<grid, 256>>>(w_proj, b_proj, ao_p, out, x, CH);
    }
}

// round 15
// speedup vs baseline: 1.0002x; 1.0002x over previous
#include <cuda_runtime.h>
#include <cuda_fp16.h>
#include <cstdint>
#include <math.h>

// Problem constants
constexpr int BATCH = 4;
constexpr int CH    = 256;
constexpr int SPA   = 4096;
constexpr int NGRP  = 8;
constexpr int CPG   = CH / NGRP;
constexpr int NH    = 4;
constexpr int HD    = CH / NH;    // 64
constexpr float EPS = 1e-5f;
constexpr float SCALE = 0.125f;

constexpr int GRP_ELEMS = CPG * SPA;
constexpr int PARTS = 32;

// Scratch
__device__ __half g_qkv[(size_t)BATCH * 3*CH * SPA];  // 24 MB
__device__ __half g_ao [(size_t)BATCH * CH  * SPA];   // 8 MB
__device__ float g_part[BATCH * NGRP][PARTS][2];
__device__ float g_ga[BATCH * CH];
__device__ float g_be[BATCH * CH];

// ---------------------------------------------------------------------------
// Helpers
// ---------------------------------------------------------------------------
__device__ __forceinline__ uint32_t smem_u32(const void* p) {
    return (uint32_t)__cvta_generic_to_shared(p);
}
__device__ __forceinline__ uint32_t packh(float lo, float hi) {
    __half2 t = __floats2half2_rn(lo, hi);   // .x = lo = low 16 bits
    return *reinterpret_cast<uint32_t*>(&t);
}
__device__ __forceinline__ uint32_t h2exp2(uint32_t a) {
    uint32_t r;
    asm("ex2.approx.f16x2 %0, %1;" : "=r"(r) : "r"(a));
    return r;
}
__device__ __forceinline__ void mma_f16(float* d, const uint32_t* a,
                                        const uint32_t* b) {
    asm volatile(
        "mma.sync.aligned.m16n8k16.row.col.f32.f16.f16.f32 "
        "{%0,%1,%2,%3}, {%4,%5,%6,%7}, {%8,%9}, {%0,%1,%2,%3};\n"
        : "+f"(d[0]), "+f"(d[1]), "+f"(d[2]), "+f"(d[3])
        : "r"(a[0]), "r"(a[1]), "r"(a[2]), "r"(a[3]), "r"(b[0]), "r"(b[1]));
}
__device__ __forceinline__ void ldsm_x4(uint32_t* r, uint32_t addr) {
    asm volatile("ldmatrix.sync.aligned.m8n8.x4.shared.b16 {%0,%1,%2,%3}, [%4];\n"
                 : "=r"(r[0]), "=r"(r[1]), "=r"(r[2]), "=r"(r[3]) : "r"(addr));
}
__device__ __forceinline__ void ldsm_x4_t(uint32_t* r, uint32_t addr) {
    asm volatile("ldmatrix.sync.aligned.m8n8.x4.trans.shared.b16 {%0,%1,%2,%3}, [%4];\n"
                 : "=r"(r[0]), "=r"(r[1]), "=r"(r[2]), "=r"(r[3]) : "r"(addr));
}
__device__ __forceinline__ void cpa(uint32_t dst, const void* src) {
    asm volatile("cp.async.cg.shared.global [%0], [%1], 16;\n" :: "r"(dst), "l"(src));
}
#define CP_COMMIT() asm volatile("cp.async.commit_group;\n" ::: "memory")
#define CP_WAIT0()  asm volatile("cp.async.wait_group 0;\n" ::: "memory")
#define CP_WAIT1()  asm volatile("cp.async.wait_group 1;\n" ::: "memory")

// ---------------------------------------------------------------------------
// GroupNorm stats
// ---------------------------------------------------------------------------
__global__ __launch_bounds__(256) void k_gn_part(const float* __restrict__ x) {
    int part = blockIdx.x & (PARTS - 1);
    int bg   = blockIdx.x / PARTS;
    const float4* base = reinterpret_cast<const float4*>(x + (size_t)bg * GRP_ELEMS)
                         + (size_t)part * (GRP_ELEMS / PARTS / 4);
    const int n4 = GRP_ELEMS / PARTS / 4;
    float s = 0.f, s2 = 0.f;
    for (int i = threadIdx.x; i < n4; i += 256) {
        float4 v = base[i];
        s  += v.x + v.y + v.z + v.w;
        s2 += v.x*v.x + v.y*v.y + v.z*v.z + v.w*v.w;
    }
    __shared__ float sh[16];
    for (int o = 16; o; o >>= 1) {
        s  += __shfl_xor_sync(0xffffffffu, s,  o);
        s2 += __shfl_xor_sync(0xffffffffu, s2, o);
    }
    if ((threadIdx.x & 31) == 0) { int w = threadIdx.x >> 5; sh[w*2] = s; sh[w*2+1] = s2; }
    __syncthreads();
    if (threadIdx.x == 0) {
        float a = 0.f, b = 0.f;
        #pragma unroll
        for (int i = 0; i < 8; i++) { a += sh[i*2]; b += sh[i*2+1]; }
        g_part[bg][part][0] = a; g_part[bg][part][1] = b;
    }
}

// finalize stats + per-(b,c) GN coefficients (ga, be)
__global__ __launch_bounds__(1024) void k_gn_final(const float* __restrict__ gamma,
                                                   const float* __restrict__ beta) {
    __shared__ float sm_m[32], sm_r[32];
    int t = threadIdx.x;
    if (t < BATCH * NGRP) {
        float s = 0.f, s2 = 0.f;
        #pragma unroll
        for (int p = 0; p < PARTS; p++) { s += g_part[t][p][0]; s2 += g_part[t][p][1]; }
        const float invN = 1.0f / (float)GRP_ELEMS;
        float mean = s * invN;
        float var  = s2 * invN - mean * mean;
        sm_m[t] = mean; sm_r[t] = rsqrtf(var + EPS);
    }
    __syncthreads();
    if (t < BATCH * CH) {
        int b = t >> 8, c = t & 255;
        int bg = b * NGRP + (c >> 5);
        float ga = gamma[c] * sm_r[bg];
        g_ga[t] = ga;
        g_be[t] = beta[c] - sm_m[bg] * ga;
    }
}

// ---------------------------------------------------------------------------
// f16 mma GEMM: Y[b][o][s] = sum_c W[o][c]*X[b][c][s] + bias (+resid)
// GN=true: X is fp32 `x`, normalized on the fly via g_ga/g_be.
// GN=false: X is __half (g_ao).
// ---------------------------------------------------------------------------
template<bool GN, bool RESID, typename OT>
__global__ __launch_bounds__(256, 2) void k_gemm(const float* __restrict__ Wm,
                                                 const float* __restrict__ bias,
                                                 const void* __restrict__ Xv,
                                                 OT* __restrict__ Y,
                                                 const float* __restrict__ resid,
                                                 int M) {
    __shared__ __half As[128 * 40];
    __shared__ __half Bs[32 * 136];

    const int b  = blockIdx.z;
    const int o0 = blockIdx.y * 128;
    const int s0 = blockIdx.x * 128;
    const int tid = threadIdx.x, lane = tid & 31, wid = tid >> 5;
    const int wm = wid & 3, wn = wid >> 2;
    const int lrow = lane & 7, lmat = lane >> 3;

    float acc[2][8][4] = {};

    for (int k0 = 0; k0 < CH; k0 += 32) {
        // A: W tile fp32 -> f16
        #pragma unroll
        for (int r = 0; r < 4; r++) {
            int i = tid + r * 256;
            int row = i >> 3, kq = (i & 7) * 4;
            float4 w4 = *reinterpret_cast<const float4*>(
                            Wm + (size_t)(o0 + row) * CH + k0 + kq);
            uint2 wp = {packh(w4.x, w4.y), packh(w4.z, w4.w)};
            *reinterpret_cast<uint2*>(&As[row * 40 + kq]) = wp;
        }
        // B tile
        #pragma unroll
        for (int r = 0; r < 2; r++) {
            int i = tid + r * 256;
            int kr = i >> 4, s8 = (i & 15) * 8;
            if (GN) {
                const float* Xb = (const float*)Xv + (size_t)b * CH * SPA;
                const float* xp = Xb + (size_t)(k0 + kr) * SPA + s0 + s8;
                float ga = g_ga[b * CH + k0 + kr];
                float be = g_be[b * CH + k0 + kr];
                float4 x0 = *reinterpret_cast<const float4*>(xp);
                float4 x1 = *reinterpret_cast<const float4*>(xp + 4);
                uint4 wv;
                wv.x = packh(x0.x*ga+be, x0.y*ga+be);
                wv.y = packh(x0.z*ga+be, x0.w*ga+be);
                wv.z = packh(x1.x*ga+be, x1.y*ga+be);
                wv.w = packh(x1.z*ga+be, x1.w*ga+be);
                *reinterpret_cast<uint4*>(&Bs[kr * 136 + s8]) = wv;
            } else {
                const __half* Xb = (const __half*)Xv + (size_t)b * CH * SPA;
                uint4 xv = *reinterpret_cast<const uint4*>(
                                Xb + (size_t)(k0 + kr) * SPA + s0 + s8);
                *reinterpret_cast<uint4*>(&Bs[kr * 136 + s8]) = xv;
            }
        }
        __syncthreads();

        #pragma unroll
        for (int kk = 0; kk < 32; kk += 16) {
            uint32_t a[2][4];
            #pragma unroll
            for (int mt = 0; mt < 2; mt++) {
                uint32_t ad = smem_u32(&As[(wm*32 + mt*16 + (lmat & 1)*8 + lrow)*40
                                           + kk + (lmat >> 1)*8]);
                ldsm_x4(a[mt], ad);
            }
            #pragma unroll
            for (int ntp = 0; ntp < 8; ntp += 2) {
                uint32_t bf[4];
                uint32_t ad = smem_u32(&Bs[(kk + (lmat & 1)*8 + lrow)*136
                                           + wn*64 + (ntp + (lmat >> 1))*8]);
                ldsm_x4_t(bf, ad);
                #pragma unroll
                for (int mt = 0; mt < 2; mt++) {
                    mma_f16(acc[mt][ntp],     a[mt], bf);
                    mma_f16(acc[mt][ntp + 1], a[mt], bf + 2);
                }
            }
        }
        __syncthreads();
    }

    #pragma unroll
    for (int mt = 0; mt < 2; mt++) {
        int row0 = o0 + wm * 32 + mt * 16 + (lane >> 2);
        float bv0 = bias[row0], bv1 = bias[row0 + 8];
        #pragma unroll
        for (int nt = 0; nt < 8; nt++) {
            int col = s0 + wn * 64 + nt * 8 + 2 * (lane & 3);
            size_t off0 = ((size_t)b * M + row0) * SPA + col;
            size_t off1 = ((size_t)b * M + row0 + 8) * SPA + col;
            float r00 = acc[mt][nt][0] + bv0, r01 = acc[mt][nt][1] + bv0;
            float r10 = acc[mt][nt][2] + bv1, r11 = acc[mt][nt][3] + bv1;
            if (RESID) {
                float2 x0 = *reinterpret_cast<const float2*>(&resid[off0]);
                float2 x1 = *reinterpret_cast<const float2*>(&resid[off1]);
                r00 += x0.x; r01 += x0.y; r10 += x1.x; r11 += x1.y;
            }
            if (sizeof(OT) == 2) {
                uint32_t p0 = packh(r00, r01), p1 = packh(r10, r11);
                *reinterpret_cast<uint32_t*>(&Y[off0]) = p0;
                *reinterpret_cast<uint32_t*>(&Y[off1]) = p1;
            } else {
                *reinterpret_cast<float2*>(&Y[off0]) = make_float2(r00, r01);
                *reinterpret_cast<float2*>(&Y[off1]) = make_float2(r10, r11);
            }
        }
    }
}

// ---------------------------------------------------------------------------
// Flash attention, f16 mma + ldmatrix, cp.async double-buffered K/V.
// Block = (b,h) x 128 queries; warp w owns q rows [w*16, w*16+16), full keys.
// Q/K/V in [d][*] SMEM layout.
// ---------------------------------------------------------------------------
constexpr int QT = 128;
constexpr int KT = 64;
constexpr int NTILE = SPA / KT;   // 64
constexpr int QS_STR = 136;       // halves
constexpr int KV_STR = 72;        // halves

constexpr int SM_Q  = 0;                       // 64*136*2 = 17408
constexpr int SM_K0 = 17408;                   // 64*72*2  = 9216
constexpr int SM_K1 = SM_K0 + 9216;
constexpr int SM_V0 = SM_K1 + 9216;
constexpr int SM_V1 = SM_V0 + 9216;
constexpr int SM_ATTN = SM_V1 + 9216;          // 54272

__global__ __launch_bounds__(256, 2) void k_attn() {
    extern __shared__ uint8_t smraw[];
    __half* Qs = reinterpret_cast<__half*>(smraw + SM_Q);
    __half* Ks[2] = { reinterpret_cast<__half*>(smraw + SM_K0),
                      reinterpret_cast<__half*>(smraw + SM_K1) };
    __half* Vs[2] = { reinterpret_cast<__half*>(smraw + SM_V0),
                      reinterpret_cast<__half*>(smraw + SM_V1) };

    const int bh = blockIdx.y, b = bh >> 2, h = bh & 3;
    const __half* qb = g_qkv + ((size_t)b * 3 * CH + h * HD) * SPA;
    const __half* kb = qb + (size_t)CH * SPA;
    const __half* vb = qb + (size_t)2 * CH * SPA;
    const int q0 = blockIdx.x * QT;
    const int tid = threadIdx.x, lane = tid & 31, w = tid >> 5;
    const int lrow = lane & 7, lmat = lane >> 3;

    const uint32_t qs_a = smem_u32(Qs);
    const uint32_t ks_a[2] = { smem_u32(Ks[0]), smem_u32(Ks[1]) };
    const uint32_t vs_a[2] = { smem_u32(Vs[0]), smem_u32(Vs[1]) };

    // prologue: Q + K0/V0 (group A), K1/V1 (group B)
    #pragma unroll
    for (int r = 0; r < 4; r++) {           // Q: 1024 chunks of 16B
        int i = tid + r * 256;
        int dd = i >> 4, q8 = (i & 15) * 8;
        cpa(qs_a + (dd * QS_STR + q8) * 2, qb + (size_t)dd * SPA + q0 + q8);
    }
    #pragma unroll
    for (int r = 0; r < 2; r++) {           // K0 + V0: 512 chunks each
        int i = tid + r * 256;
        int dd = i >> 3, k8 = (i & 7) * 8;
        cpa(ks_a[0] + (dd * KV_STR + k8) * 2, kb + (size_t)dd * SPA + k8);
        cpa(vs_a[0] + (dd * KV_STR + k8) * 2, vb + (size_t)dd * SPA + k8);
    }
    CP_COMMIT();
    #pragma unroll
    for (int r = 0; r < 2; r++) {
        int i = tid + r * 256;
        int dd = i >> 3, k8 = (i & 7) * 8;
        cpa(ks_a[1] + (dd * KV_STR + k8) * 2, kb + (size_t)dd * SPA + KT + k8);
        cpa(vs_a[1] + (dd * KV_STR + k8) * 2, vb + (size_t)dd * SPA + KT + k8);
    }
    CP_COMMIT();
    CP_WAIT1();           // Q + tile0 ready
    __syncthreads();

    // hoist Q A-fragments
    uint32_t qa[4][4];
    #pragma unroll
    for (int kk4 = 0; kk4 < 4; kk4++) {
        uint32_t ad = smem_u32(&Qs[(kk4*16 + (lmat >> 1)*8 + lrow) * QS_STR
                                   + w*16 + (lmat & 1)*8]);
        ldsm_x4_t(qa[kk4], ad);
    }

    float m2[2] = {-INFINITY, -INFINITY};
    float l [2] = {0.f, 0.f};
    float o_acc[8][4] = {};
    const float CF = SCALE * 1.44269504f;

    for (int i = 0; i < NTILE; i++) {
        const __half* Kb = Ks[i & 1];
        const __half* Vb = Vs[i & 1];

        // S = Q K^T
        float sacc[8][4] = {};
        #pragma unroll
        for (int kk4 = 0; kk4 < 4; kk4++) {
            #pragma unroll
            for (int ntp = 0; ntp < 8; ntp += 2) {
                uint32_t bf[4];
                uint32_t ad = smem_u32(&Kb[(kk4*16 + (lmat & 1)*8 + lrow) * KV_STR
                                           + (ntp + (lmat >> 1))*8]);
                ldsm_x4_t(bf, ad);
                mma_f16(sacc[ntp],     qa[kk4], bf);
                mma_f16(sacc[ntp + 1], qa[kk4], bf + 2);
            }
        }

        // online softmax: p as f16x2 via ex2.approx.f16x2 (= PV A-frag regs)
        uint32_t pp[8][2];
        #pragma unroll
        for (int rh = 0; rh < 2; rh++) {
            float mx = -1e30f;
            #pragma unroll
            for (int nt = 0; nt < 8; nt++)
                mx = fmaxf(mx, fmaxf(sacc[nt][rh*2], sacc[nt][rh*2+1]));
            mx *= CF;
            mx = fmaxf(mx, __shfl_xor_sync(0xffffffffu, mx, 1));
            mx = fmaxf(mx, __shfl_xor_sync(0xffffffffu, mx, 2));
            float mnew = fmaxf(m2[rh], mx);
            __half2 sum2 = __floats2half2_rn(0.f, 0.f);
            #pragma unroll
            for (int nt = 0; nt < 8; nt++) {
                uint32_t sp = packh(sacc[nt][rh*2]   * CF - mnew,
                                    sacc[nt][rh*2+1] * CF - mnew);
                uint32_t ph = h2exp2(sp);
                pp[nt][rh] = ph;
                sum2 = __hadd2(sum2, *reinterpret_cast<__half2*>(&ph));
            }
            float2 sf = __half22float2(sum2);
            float rs = sf.x + sf.y;
            rs += __shfl_xor_sync(0xffffffffu, rs, 1);
            rs += __shfl_xor_sync(0xffffffffu, rs, 2);
            if (mx > m2[rh]) {          // max moved: rescale
                float alpha = exp2f(m2[rh] - mnew);
                #pragma unroll
                for (int nt = 0; nt < 8; nt++) {
                    o_acc[nt][rh*2]   *= alpha;
                    o_acc[nt][rh*2+1] *= alpha;
                }
                l[rh] = l[rh] * alpha + rs;
                m2[rh] = mnew;
            } else {
                l[rh] += rs;
            }
        }

        // O += P V
        #pragma unroll
        for (int j = 0; j < 4; j++) {
            uint32_t pa[4] = {pp[2*j][0], pp[2*j][1], pp[2*j+1][0], pp[2*j+1][1]};
            #pragma unroll
            for (int dt = 0; dt < 8; dt += 2) {
                uint32_t bv[4];
                uint32_t ad = smem_u32(&Vb[((dt + (lmat >> 1))*8 + lrow) * KV_STR
                                           + j*16 + (lmat & 1)*8]);
                ldsm_x4(bv, ad);
                mma_f16(o_acc[dt],     pa, bv);
                mma_f16(o_acc[dt + 1], pa, bv + 2);
            }
        }

        // rotate buffers: done reading buf[i&1]; prefetch tile i+2 into it
        __syncthreads();
        if (i + 2 < NTILE) {
            int t0 = (i + 2) * KT;
            uint32_t ka = ks_a[i & 1], va = vs_a[i & 1];
            #pragma unroll
            for (int r = 0; r < 2; r++) {
                int c = tid + r * 256;
                int dd = c >> 3, k8 = (c & 7) * 8;
                cpa(ka + (dd * KV_STR + k8) * 2, kb + (size_t)dd * SPA + t0 + k8);
                cpa(va + (dd * KV_STR + k8) * 2, vb + (size_t)dd * SPA + t0 + k8);
            }
            CP_COMMIT();
        }
        if (i + 1 < NTILE) {
            if (i + 2 < NTILE) { CP_WAIT1(); } else { CP_WAIT0(); }
            __syncthreads();
        }
    }

    // normalize + write f16: g_ao[b][h*64+dd][q0+qr]
    __half* ob = g_ao + ((size_t)b * CH + h * HD) * SPA + q0;
    #pragma unroll
    for (int rh = 0; rh < 2; rh++) {
        float inv = 1.0f / l[rh];
        int qr = w * 16 + rh * 8 + (lane >> 2);
        #pragma unroll
        for (int nt = 0; nt < 8; nt++) {
            int dd = nt * 8 + 2 * (lane & 3);
            ob[(size_t)dd * SPA + qr]       = __float2half(o_acc[nt][rh*2]   * inv);
            ob[(size_t)(dd + 1) * SPA + qr] = __float2half(o_acc[nt][rh*2+1] * inv);
        }
    }
}

// ---------------------------------------------------------------------------
extern "C" void kernel_launch(void* const* d_in, const int* in_sizes, int n_in,
                              void* d_out, int out_size) {
    const float* x      = (const float*)d_in[0];
    const float* gamma  = (const float*)d_in[1];
    const float* beta   = (const float*)d_in[2];
    const float* w_qkv  = (const float*)d_in[3];
    const float* b_qkv  = (const float*)d_in[4];
    const float* w_proj = (const float*)d_in[5];
    const float* b_proj = (const float*)d_in[6];
    float* out = (float*)d_out;

    __half *qkv_p, *ao_p;
    cudaGetSymbolAddress((void**)&qkv_p, g_qkv);
    cudaGetSymbolAddress((void**)&ao_p,  g_ao);

    cudaFuncSetAttribute(k_attn, cudaFuncAttributeMaxDynamicSharedMemorySize, SM_ATTN);

    // GroupNorm stats + coefficients
    k_gn_part <<<BATCH * NGRP * PARTS, 256>>>(x);
    k_gn_final<<<1, 1024>>>(gamma, beta);

    // QKV GEMM with fused GN (M = 768), f16 out
    {
        dim3 grid(SPA / 128, (3 * CH) / 128, BATCH);
        k_gemm<true, false, __half><<<grid, 256>>>(w_qkv, b_qkv, x, qkv_p,
                                                   nullptr, 3 * CH);
    }

    // f16 flash attention
    {
        dim3 grid(SPA / QT, BATCH * NH);
        k_attn<<<grid, 256, SM_ATTN>>>();
    }

    // Proj GEMM + residual (M = 256), fp32 out
    {
        dim3 grid(SPA / 128, CH / 128, BATCH);
        k_gemm<false, true, float><<<grid, 256>>>(w_proj, b_proj, ao_p, out, x, CH);
    }
}